// round 1
// baseline (speedup 1.0000x reference)
#include <cuda_runtime.h>
#include <math.h>

// ---------------------------------------------------------------------------
// Problem constants
// ---------------------------------------------------------------------------
#define DM   768          // d_model
#define DI   1536         // d_inner
#define NS   16           // d_state
#define RK   48           // dt_rank
#define LC   6            // seq len
#define BT   1024         // batch
#define MR   (BT * LC)    // 6144 rows

// ---------------------------------------------------------------------------
// Scratch layout (single __device__ array, no allocations)
// ---------------------------------------------------------------------------
static const size_t SZ_XZ  = (size_t)MR * 2 * DI;   // 18874368
static const size_t SZ_XC  = (size_t)MR * DI;       //  9437184
static const size_t SZ_XD  = (size_t)MR * 80;       //   491520
static const size_t SZ_R   = (size_t)MR * DM;       //  4718592

#define OFF_XZ_F  ((size_t)0)
#define OFF_XZ_B  (OFF_XZ_F + 18874368u)
#define OFF_XC_F  (OFF_XZ_B + 18874368u)
#define OFF_XC_B  (OFF_XC_F + 9437184u)
#define OFF_XDP_F (OFF_XC_B + 9437184u)           // 4 split-K partials
#define OFF_XDP_B (OFF_XDP_F + 4u*491520u)
#define OFF_XD_F  (OFF_XDP_B + 4u*491520u)
#define OFF_XD_B  (OFF_XD_F + 491520u)
#define OFF_DT_F  (OFF_XD_B + 491520u)
#define OFF_DT_B  (OFF_DT_F + 9437184u)
#define OFF_Y_F   (OFF_DT_B + 9437184u)
#define OFF_Y_B   (OFF_Y_F + 9437184u)
#define OFF_R     (OFF_Y_B + 9437184u)
#define SCRATCH_TOTAL (OFF_R + 4718592u)

__device__ float g_scratch[SCRATCH_TOTAL];

// ---------------------------------------------------------------------------
// Generic fp32 GEMM (NT):  C[M,N] = A[M,K] (row, lda) @ B[N,K]^T (row, ldb)
// Requirements (guaranteed by call sites): M%128==0, N%128==0, K%8==0,
// lda%4==0, ldb%4==0.
// op: 0 = store (+addsrc), 1 = accumulate into C, 2 = softplus(acc + bias)
// ---------------------------------------------------------------------------
__global__ __launch_bounds__(256, 2)
void sgemm_nt(int M, int N, int K,
              const float* __restrict__ A, int lda,
              const float* __restrict__ B, int ldb,
              float* __restrict__ C, int ldc,
              const float* __restrict__ addsrc,
              const float* __restrict__ bias,
              int op)
{
    __shared__ float As[8][128];
    __shared__ float Bs[8][128];
    const int tid = threadIdx.x;
    const int bm = blockIdx.y * 128;
    const int bn = blockIdx.x * 128;
    const int ir = tid >> 1;
    const int ic = (tid & 1) * 4;
    const float* Ap = A + (size_t)(bm + ir) * lda + ic;
    const float* Bp = B + (size_t)(bn + ir) * ldb + ic;

    float acc[8][8];
#pragma unroll
    for (int i = 0; i < 8; i++)
#pragma unroll
        for (int j = 0; j < 8; j++) acc[i][j] = 0.f;

    const int tr = (tid >> 4) * 8;
    const int tc = (tid & 15) * 8;

    for (int k0 = 0; k0 < K; k0 += 8) {
        float4 a4 = *reinterpret_cast<const float4*>(Ap + k0);
        float4 b4 = *reinterpret_cast<const float4*>(Bp + k0);
        As[ic + 0][ir] = a4.x; As[ic + 1][ir] = a4.y;
        As[ic + 2][ir] = a4.z; As[ic + 3][ir] = a4.w;
        Bs[ic + 0][ir] = b4.x; Bs[ic + 1][ir] = b4.y;
        Bs[ic + 2][ir] = b4.z; Bs[ic + 3][ir] = b4.w;
        __syncthreads();
#pragma unroll
        for (int k = 0; k < 8; k++) {
            float ra[8], rb[8];
            *reinterpret_cast<float4*>(&ra[0]) = *reinterpret_cast<const float4*>(&As[k][tr]);
            *reinterpret_cast<float4*>(&ra[4]) = *reinterpret_cast<const float4*>(&As[k][tr + 4]);
            *reinterpret_cast<float4*>(&rb[0]) = *reinterpret_cast<const float4*>(&Bs[k][tc]);
            *reinterpret_cast<float4*>(&rb[4]) = *reinterpret_cast<const float4*>(&Bs[k][tc + 4]);
#pragma unroll
            for (int i = 0; i < 8; i++)
#pragma unroll
                for (int j = 0; j < 8; j++)
                    acc[i][j] += ra[i] * rb[j];
        }
        __syncthreads();
    }

#pragma unroll
    for (int i = 0; i < 8; i++) {
        const int m = bm + tr + i;
#pragma unroll
        for (int j = 0; j < 8; j++) {
            const int n = bn + tc + j;
            const size_t idx = (size_t)m * ldc + n;
            float v = acc[i][j];
            if (addsrc) v += addsrc[idx];
            if (bias)   v += bias[n];
            if (op == 1) v += C[idx];
            if (op == 2) v = (v > 20.f) ? v : log1pf(expf(v));
            C[idx] = v;
        }
    }
}

// ---------------------------------------------------------------------------
// Depthwise causal conv (fwd) + anti-causal conv (bwd, original-l indexing)
// followed by SiLU. Reads xi halves of xz_f / xz_b, writes xc_f / xc_b.
// ---------------------------------------------------------------------------
__global__ void conv_silu_kernel(const float* __restrict__ fw, const float* __restrict__ fb,
                                 const float* __restrict__ bw, const float* __restrict__ bb)
{
    const int idx = blockIdx.x * 256 + threadIdx.x;   // exactly BT*DI threads
    const int b = idx / DI, d = idx % DI;
    const float* xzf = g_scratch + OFF_XZ_F;
    const float* xzb = g_scratch + OFF_XZ_B;
    float* xcf = g_scratch + OFF_XC_F;
    float* xcb = g_scratch + OFF_XC_B;

    float wf[4], wbk[4];
#pragma unroll
    for (int k = 0; k < 4; k++) { wf[k] = fw[k * DI + d]; wbk[k] = bw[k * DI + d]; }

    float xf[6], xb[6];
#pragma unroll
    for (int l = 0; l < 6; l++) {
        xf[l] = xzf[(size_t)(b * 6 + l) * (2 * DI) + d];
        xb[l] = xzb[(size_t)(b * 6 + l) * (2 * DI) + d];
    }
    const float cbf = fb[d], cbb = bb[d];

#pragma unroll
    for (int l = 0; l < 6; l++) {
        float af = cbf, ab = cbb;
#pragma unroll
        for (int k = 0; k < 4; k++) {
            const int lf = l + k - 3;
            if (lf >= 0) af += wf[k] * xf[lf];
            const int lb = l + 3 - k;
            if (lb < 6) ab += wbk[k] * xb[lb];
        }
        const float sf = af / (1.f + expf(-af));
        const float sb = ab / (1.f + expf(-ab));
        xcf[(size_t)(b * 6 + l) * DI + d] = sf;
        xcb[(size_t)(b * 6 + l) * DI + d] = sb;
    }
}

// ---------------------------------------------------------------------------
// x_proj GEMM, skinny-N (M=6144, N=80, K=1536), deterministic split-K=4.
// Each block computes a 64x80 tile over a 384-wide K slice into its partial.
// ---------------------------------------------------------------------------
__global__ __launch_bounds__(256)
void xproj_kernel(const float* __restrict__ A, const float* __restrict__ Bw,
                  float* __restrict__ Cpart)
{
    __shared__ float As[16][64];
    __shared__ float Bs[16][80];
    const int tid = threadIdx.x;
    const int bm = blockIdx.x * 64;
    const int ks = blockIdx.y;
    const int irA = tid >> 2, icA = (tid & 3) * 4;
    const int tr = (tid >> 4) * 4, tc = (tid & 15) * 5;

    float acc[4][5];
#pragma unroll
    for (int i = 0; i < 4; i++)
#pragma unroll
        for (int j = 0; j < 5; j++) acc[i][j] = 0.f;

    const int kbeg = ks * 384;
    for (int k0 = kbeg; k0 < kbeg + 384; k0 += 16) {
        float4 a4 = *reinterpret_cast<const float4*>(A + (size_t)(bm + irA) * DI + k0 + icA);
        As[icA + 0][irA] = a4.x; As[icA + 1][irA] = a4.y;
        As[icA + 2][irA] = a4.z; As[icA + 3][irA] = a4.w;
#pragma unroll
        for (int t = 0; t < 5; t++) {
            const int li = tid + t * 256;
            const int n = li >> 4, k = li & 15;
            Bs[k][n] = Bw[(size_t)n * DI + k0 + k];
        }
        __syncthreads();
#pragma unroll
        for (int k = 0; k < 16; k++) {
            float ra[4], rb[5];
#pragma unroll
            for (int i = 0; i < 4; i++) ra[i] = As[k][tr + i];
#pragma unroll
            for (int j = 0; j < 5; j++) rb[j] = Bs[k][tc + j];
#pragma unroll
            for (int i = 0; i < 4; i++)
#pragma unroll
                for (int j = 0; j < 5; j++) acc[i][j] += ra[i] * rb[j];
        }
        __syncthreads();
    }

    float* Cp = Cpart + (size_t)ks * (size_t)MR * 80;
#pragma unroll
    for (int i = 0; i < 4; i++)
#pragma unroll
        for (int j = 0; j < 5; j++)
            Cp[(size_t)(bm + tr + i) * 80 + tc + j] = acc[i][j];
}

// Sum the 4 split-K partials for both directions (deterministic).
__global__ void reduce4_kernel()
{
    const size_t S = (size_t)MR * 80;
    const size_t i = (size_t)blockIdx.x * 256 + threadIdx.x;   // grid covers S
    const float* pf = g_scratch + OFF_XDP_F;
    const float* pb = g_scratch + OFF_XDP_B;
    g_scratch[OFF_XD_F + i] = (pf[i] + pf[i + S]) + (pf[i + 2 * S] + pf[i + 3 * S]);
    g_scratch[OFF_XD_B + i] = (pb[i] + pb[i + S]) + (pb[i + 2 * S] + pb[i + 3 * S]);
}

// ---------------------------------------------------------------------------
// Selective scan + skip (u*D) + SiLU(z) gate. One thread per (b, d).
// rev=0: l = 0..5; rev=1: l = 5..0 (backward direction in original indexing).
// ---------------------------------------------------------------------------
__global__ __launch_bounds__(256)
void scan_kernel(int rev,
                 const float* __restrict__ dtb,   // (MR, DI)
                 const float* __restrict__ ub,    // xc (MR, DI)
                 const float* __restrict__ xzb,   // (MR, 2*DI) for z gate
                 const float* __restrict__ xdb,   // (MR, 80) for B, C
                 const float* __restrict__ Alog,  // (DI, 16)
                 const float* __restrict__ Dp,    // (DI)
                 float* __restrict__ yb)          // (MR, DI)
{
    __shared__ float sB[6][16];
    __shared__ float sC[6][16];
    const int tid = threadIdx.x;
    const int b = blockIdx.y;
    const int d = blockIdx.x * 256 + tid;

    if (tid < 96) {
        const int l = tid >> 4, n = tid & 15;
        sB[l][n] = xdb[(size_t)(b * 6 + l) * 80 + 48 + n];
    } else if (tid < 192) {
        const int t = tid - 96;
        const int l = t >> 4, n = t & 15;
        sC[l][n] = xdb[(size_t)(b * 6 + l) * 80 + 64 + n];
    }
    __syncthreads();

    float A[16];
#pragma unroll
    for (int n = 0; n < 16; n++) A[n] = -expf(Alog[(size_t)d * 16 + n]);

    float h[16];
#pragma unroll
    for (int n = 0; n < 16; n++) h[n] = 0.f;
    const float Dd = Dp[d];

    for (int s = 0; s < 6; s++) {
        const int l = rev ? (5 - s) : s;
        const size_t row = (size_t)(b * 6 + l);
        const float dt = dtb[row * DI + d];
        const float u  = ub[row * DI + d];
        const float dtu = dt * u;
        float y = 0.f;
#pragma unroll
        for (int n = 0; n < 16; n++) {
            h[n] = expf(dt * A[n]) * h[n] + dtu * sB[l][n];
            y += h[n] * sC[l][n];
        }
        y += u * Dd;
        const float z = xzb[row * (2 * DI) + DI + d];
        y *= z / (1.f + expf(-z));
        yb[row * DI + d] = y;
    }
}

// ---------------------------------------------------------------------------
// LayerNorm over the residual buffer r (MR x 768) -> d_out.
// ---------------------------------------------------------------------------
__device__ __forceinline__ float block_reduce_sum(float v)
{
    __shared__ float red[8];
    const int lane = threadIdx.x & 31, w = threadIdx.x >> 5;
#pragma unroll
    for (int o = 16; o; o >>= 1) v += __shfl_xor_sync(0xffffffffu, v, o);
    __syncthreads();                 // protect smem reuse across calls
    if (lane == 0) red[w] = v;
    __syncthreads();
    return (red[0] + red[1]) + (red[2] + red[3]) +
           (red[4] + red[5]) + (red[6] + red[7]);
}

__global__ __launch_bounds__(256)
void ln_kernel(const float* __restrict__ g, const float* __restrict__ bta,
               float* __restrict__ out)
{
    const int row = blockIdx.x, tid = threadIdx.x;
    const float* r = g_scratch + OFF_R + (size_t)row * DM;
    const float v0 = r[tid], v1 = r[tid + 256], v2 = r[tid + 512];
    const float tot = block_reduce_sum(v0 + v1 + v2);
    const float mu = tot * (1.f / 768.f);
    const float d0 = v0 - mu, d1 = v1 - mu, d2 = v2 - mu;
    const float tot2 = block_reduce_sum(d0 * d0 + d1 * d1 + d2 * d2);
    const float inv = rsqrtf(tot2 * (1.f / 768.f) + 1e-5f);
    float* o = out + (size_t)row * DM;
    o[tid]       = d0 * inv * g[tid]       + bta[tid];
    o[tid + 256] = d1 * inv * g[tid + 256] + bta[tid + 256];
    o[tid + 512] = d2 * inv * g[tid + 512] + bta[tid + 512];
}

// ---------------------------------------------------------------------------
// Launch
// ---------------------------------------------------------------------------
extern "C" void kernel_launch(void* const* d_in, const int* in_sizes, int n_in,
                              void* d_out, int out_size)
{
    const float* x     = (const float*)d_in[0];
    const float* f_inw = (const float*)d_in[1];
    const float* f_cw  = (const float*)d_in[2];
    const float* f_cb  = (const float*)d_in[3];
    const float* f_xp  = (const float*)d_in[4];
    const float* f_dtw = (const float*)d_in[5];
    const float* f_dtb = (const float*)d_in[6];
    const float* f_Al  = (const float*)d_in[7];
    const float* f_D   = (const float*)d_in[8];
    const float* f_ow  = (const float*)d_in[9];
    const float* b_inw = (const float*)d_in[10];
    const float* b_cw  = (const float*)d_in[11];
    const float* b_cb  = (const float*)d_in[12];
    const float* b_xp  = (const float*)d_in[13];
    const float* b_dtw = (const float*)d_in[14];
    const float* b_dtb = (const float*)d_in[15];
    const float* b_Al  = (const float*)d_in[16];
    const float* b_D   = (const float*)d_in[17];
    const float* b_ow  = (const float*)d_in[18];
    const float* ln_g  = (const float*)d_in[19];
    const float* ln_b  = (const float*)d_in[20];
    float* out = (float*)d_out;

    float* S = nullptr;
    cudaGetSymbolAddress((void**)&S, g_scratch);

    float* xz_f = S + OFF_XZ_F;
    float* xz_b = S + OFF_XZ_B;
    float* xc_f = S + OFF_XC_F;
    float* xc_b = S + OFF_XC_B;
    float* xdp_f = S + OFF_XDP_F;
    float* xdp_b = S + OFF_XDP_B;
    float* xd_f = S + OFF_XD_F;
    float* xd_b = S + OFF_XD_B;
    float* dt_f = S + OFF_DT_F;
    float* dt_b = S + OFF_DT_B;
    float* y_f  = S + OFF_Y_F;
    float* y_b  = S + OFF_Y_B;
    float* rbuf = S + OFF_R;

    const dim3 blk(256);

    // 1) in_proj (both directions on un-reversed x)
    sgemm_nt<<<dim3(24, 48), blk>>>(MR, 2 * DI, DM, x, DM, f_inw, DM, xz_f, 2 * DI, nullptr, nullptr, 0);
    sgemm_nt<<<dim3(24, 48), blk>>>(MR, 2 * DI, DM, x, DM, b_inw, DM, xz_b, 2 * DI, nullptr, nullptr, 0);

    // 2) depthwise conv + SiLU (fwd causal, bwd anti-causal)
    conv_silu_kernel<<<BT * DI / 256, blk>>>(f_cw, f_cb, b_cw, b_cb);

    // 3) x_proj (split-K partials, deterministic reduce)
    xproj_kernel<<<dim3(96, 4), blk>>>(xc_f, f_xp, xdp_f);
    xproj_kernel<<<dim3(96, 4), blk>>>(xc_b, b_xp, xdp_b);
    reduce4_kernel<<<(int)((size_t)MR * 80 / 256), blk>>>();

    // 4) dt projection + bias + softplus
    sgemm_nt<<<dim3(12, 48), blk>>>(MR, DI, RK, xd_f, 80, f_dtw, RK, dt_f, DI, nullptr, f_dtb, 2);
    sgemm_nt<<<dim3(12, 48), blk>>>(MR, DI, RK, xd_b, 80, b_dtw, RK, dt_b, DI, nullptr, b_dtb, 2);

    // 5) selective scan + D skip + SiLU(z) gate
    scan_kernel<<<dim3(6, BT), blk>>>(0, dt_f, xc_f, xz_f, xd_f, f_Al, f_D, y_f);
    scan_kernel<<<dim3(6, BT), blk>>>(1, dt_b, xc_b, xz_b, xd_b, b_Al, b_D, y_b);

    // 6) out_proj + residual, then LayerNorm
    sgemm_nt<<<dim3(6, 48), blk>>>(MR, DM, DI, y_f, DI, f_ow, DI, rbuf, DM, x, nullptr, 0);
    sgemm_nt<<<dim3(6, 48), blk>>>(MR, DM, DI, y_b, DI, b_ow, DI, rbuf, DM, nullptr, nullptr, 1);
    ln_kernel<<<MR, blk>>>(ln_g, ln_b, out);
}

// round 4
// speedup vs baseline: 2.0687x; 2.0687x over previous
#include <cuda_runtime.h>
#include <cuda_bf16.h>
#include <math.h>
#include <stdint.h>

// ---------------------------------------------------------------------------
// Problem constants
// ---------------------------------------------------------------------------
#define DM   768          // d_model
#define DI   1536         // d_inner
#define NS   16           // d_state
#define RK   48           // dt_rank
#define LC   6            // seq len
#define BT   1024         // batch
#define MR   (BT * LC)    // 6144 rows

// ---------------------------------------------------------------------------
// Scratch layout (single __device__ array, no allocations)
// ---------------------------------------------------------------------------
#define OFF_XZ_F  ((size_t)0)
#define OFF_XZ_B  (OFF_XZ_F + 18874368u)
#define OFF_XC_F  (OFF_XZ_B + 18874368u)
#define OFF_XC_B  (OFF_XC_F + 9437184u)
#define OFF_XDP_F (OFF_XC_B + 9437184u)           // 4 split-K partials
#define OFF_XDP_B (OFF_XDP_F + 4u*491520u)
#define OFF_XD_F  (OFF_XDP_B + 4u*491520u)
#define OFF_XD_B  (OFF_XD_F + 491520u)
#define OFF_DT_F  (OFF_XD_B + 491520u)
#define OFF_DT_B  (OFF_DT_F + 9437184u)
#define OFF_Y_F   (OFF_DT_B + 9437184u)
#define OFF_Y_B   (OFF_Y_F + 9437184u)
#define OFF_R     (OFF_Y_B + 9437184u)
#define SCRATCH_TOTAL (OFF_R + 4718592u)

__device__ float g_scratch[SCRATCH_TOTAL];

// ---------------------------------------------------------------------------
// Small PTX helpers (all legal on plain sm_103 target)
// ---------------------------------------------------------------------------
__device__ __forceinline__ uint32_t smem_to_u32(const void* p) {
    uint32_t a;
    asm("{ .reg .u64 t; cvta.to.shared.u64 t, %1; cvt.u32.u64 %0, t; }"
        : "=r"(a) : "l"(p));
    return a;
}

__device__ __forceinline__ void sts128(uint32_t addr, uint32_t r0, uint32_t r1,
                                       uint32_t r2, uint32_t r3) {
    asm volatile("st.shared.v4.b32 [%0], {%1, %2, %3, %4};"
                 :: "r"(addr), "r"(r0), "r"(r1), "r"(r2), "r"(r3) : "memory");
}

__device__ __forceinline__ void ldsm4(uint32_t addr, uint32_t* r) {
    asm volatile("ldmatrix.sync.aligned.m8n8.x4.shared.b16 {%0, %1, %2, %3}, [%4];"
                 : "=r"(r[0]), "=r"(r[1]), "=r"(r[2]), "=r"(r[3]) : "r"(addr));
}

__device__ __forceinline__ void mma16816(float* c, const uint32_t* a,
                                         uint32_t b0, uint32_t b1) {
    asm volatile(
        "mma.sync.aligned.m16n8k16.row.col.f32.bf16.bf16.f32 "
        "{%0,%1,%2,%3}, {%4,%5,%6,%7}, {%8,%9}, {%0,%1,%2,%3};"
        : "+f"(c[0]), "+f"(c[1]), "+f"(c[2]), "+f"(c[3])
        : "r"(a[0]), "r"(a[1]), "r"(a[2]), "r"(a[3]), "r"(b0), "r"(b1));
}

// fp32 pair -> (hi bf16x2, lo bf16x2); lo is the rounding residual
__device__ __forceinline__ void split2(float a0, float a1,
                                       uint32_t& hi, uint32_t& lo) {
    uint32_t h;
    asm("cvt.rn.bf16x2.f32 %0, %1, %2;" : "=r"(h) : "f"(a1), "f"(a0)); // lo half=a0
    float h0 = __uint_as_float(h << 16);
    float h1 = __uint_as_float(h & 0xffff0000u);
    float l0 = a0 - h0;
    float l1 = a1 - h1;
    asm("cvt.rn.bf16x2.f32 %0, %1, %2;" : "=r"(lo) : "f"(l1), "f"(l0));
    hi = h;
}

// ---------------------------------------------------------------------------
// Split-precision bf16 tensor-core GEMM (NT):
//   C[M,N] = A[M,K](row,lda) @ B[N,K]^T(row,ldb), fp32 in/out, ~1e-5 rel err
// via mma.sync m16n8k16: hi*hi + hi*lo + lo*hi (lo*lo dropped).
// CTA tile 128x128, BK=32, 8 warps of 32x64, double-buffered smem (64 KB).
// smem row layout: per row 128B = hi chunks 0..3 (k0..31) | lo chunks 4..7,
// 16B chunk index XOR-swizzled with (row&7) -> conflict-free ldmatrix.
// op: 0 = store (+addsrc), 1 = C += result.
// Requires M%128==0, N%128==0, K%32==0, lda%4==0, ldb%4==0.
// ---------------------------------------------------------------------------
#define MG_STAGE 32768u          // sA(16KB) + sB(16KB)
#define MG_SMEM  (2u * MG_STAGE) // 64 KB

__device__ __forceinline__ void stage_load(const float* Ag, int lda,
                                           const float* Bg, int ldb, int s,
                                           float4* pa, float4* pb)
{
    const float* p = Ag + s * 32;
    pa[0] = *reinterpret_cast<const float4*>(p);
    pa[1] = *reinterpret_cast<const float4*>(p + 4);
    p += (size_t)64 * lda;
    pa[2] = *reinterpret_cast<const float4*>(p);
    pa[3] = *reinterpret_cast<const float4*>(p + 4);
    const float* q = Bg + s * 32;
    pb[0] = *reinterpret_cast<const float4*>(q);
    pb[1] = *reinterpret_cast<const float4*>(q + 4);
    q += (size_t)64 * ldb;
    pb[2] = *reinterpret_cast<const float4*>(q);
    pb[3] = *reinterpret_cast<const float4*>(q + 4);
}

__device__ __forceinline__ void stage_store(uint32_t sbase, int buf,
                                            int lrow, int lc,
                                            const float4* pa, const float4* pb)
{
    const uint32_t abase = sbase + (uint32_t)buf * MG_STAGE;
    const uint32_t bbase = abase + 16384u;
#pragma unroll
    for (int j = 0; j < 2; j++) {
        const int r = lrow + j * 64;
        const uint32_t rb = (uint32_t)r * 128u;
        const uint32_t ohi = rb + (uint32_t)(((lc)     ^ (r & 7)) << 4);
        const uint32_t olo = rb + (uint32_t)(((lc + 4) ^ (r & 7)) << 4);
        uint32_t h0, h1, h2, h3, l0, l1, l2, l3;
        split2(pa[2*j].x,   pa[2*j].y,   h0, l0);
        split2(pa[2*j].z,   pa[2*j].w,   h1, l1);
        split2(pa[2*j+1].x, pa[2*j+1].y, h2, l2);
        split2(pa[2*j+1].z, pa[2*j+1].w, h3, l3);
        sts128(abase + ohi, h0, h1, h2, h3);
        sts128(abase + olo, l0, l1, l2, l3);
        split2(pb[2*j].x,   pb[2*j].y,   h0, l0);
        split2(pb[2*j].z,   pb[2*j].w,   h1, l1);
        split2(pb[2*j+1].x, pb[2*j+1].y, h2, l2);
        split2(pb[2*j+1].z, pb[2*j+1].w, h3, l3);
        sts128(bbase + ohi, h0, h1, h2, h3);
        sts128(bbase + olo, l0, l1, l2, l3);
    }
}

__global__ __launch_bounds__(256, 1)
void mma_gemm(int K,
              const float* __restrict__ A, int lda,
              const float* __restrict__ B, int ldb,
              float* __restrict__ C, int ldc,
              const float* __restrict__ addsrc, int op)
{
    extern __shared__ char dsm[];
    const uint32_t sbase = smem_to_u32(dsm);
    const int tid = threadIdx.x;
    const int w = tid >> 5, lane = tid & 31;
    const int bm = blockIdx.y * 128, bn = blockIdx.x * 128;
    const int wm = w & 3, wn = w >> 2;

    // loader coordinates: thread covers rows lrow, lrow+64 at k-chunk lc
    const int lrow = tid >> 2, lc = tid & 3;
    const float* Ag = A + (size_t)(bm + lrow) * lda + lc * 8;
    const float* Bg = B + (size_t)(bn + lrow) * ldb + lc * 8;

    float acc[2][8][4];
#pragma unroll
    for (int i = 0; i < 2; i++)
#pragma unroll
        for (int j = 0; j < 8; j++)
#pragma unroll
            for (int t = 0; t < 4; t++) acc[i][j][t] = 0.f;

    const int S = K / 32;
    float4 pa[4], pb[4];

    stage_load(Ag, lda, Bg, ldb, 0, pa, pb);
    stage_store(sbase, 0, lrow, lc, pa, pb);
    __syncthreads();

    // per-lane fragment address components
    const int arow0 = wm * 32 + (lane & 15);
    const int ach   = lane >> 4;
    const int brow0 = wn * 64 + (lane & 7) + ((lane >> 4) & 1) * 8;
    const int bch   = (lane >> 3) & 1;

    for (int s = 0; s < S; s++) {
        if (s + 1 < S) stage_load(Ag, lda, Bg, ldb, s + 1, pa, pb);

        const uint32_t abase = sbase + (uint32_t)(s & 1) * MG_STAGE;
        const uint32_t bbase = abase + 16384u;
#pragma unroll
        for (int k2 = 0; k2 < 2; k2++) {
            const int kh  = k2 * 2 + ach;
            const int kl  = 4 + k2 * 2 + ach;
            const int kbh = k2 * 2 + bch;
            const int kbl = 4 + k2 * 2 + bch;
            uint32_t Ahi[2][4], Alo[2][4], Bhi[4][4], Blo[4][4];
#pragma unroll
            for (int mt = 0; mt < 2; mt++) {
                const int r = arow0 + mt * 16;
                const uint32_t rb = (uint32_t)r * 128u;
                ldsm4(abase + rb + (uint32_t)((kh ^ (r & 7)) << 4), Ahi[mt]);
                ldsm4(abase + rb + (uint32_t)((kl ^ (r & 7)) << 4), Alo[mt]);
            }
#pragma unroll
            for (int np = 0; np < 4; np++) {
                const int r = brow0 + np * 16;
                const uint32_t rb = (uint32_t)r * 128u;
                ldsm4(bbase + rb + (uint32_t)((kbh ^ (r & 7)) << 4), Bhi[np]);
                ldsm4(bbase + rb + (uint32_t)((kbl ^ (r & 7)) << 4), Blo[np]);
            }
#pragma unroll
            for (int mt = 0; mt < 2; mt++)
#pragma unroll
                for (int nt = 0; nt < 8; nt++) {
                    const uint32_t* bh = &Bhi[nt >> 1][(nt & 1) * 2];
                    const uint32_t* bl = &Blo[nt >> 1][(nt & 1) * 2];
                    mma16816(acc[mt][nt], Ahi[mt], bh[0], bh[1]);
                    mma16816(acc[mt][nt], Ahi[mt], bl[0], bl[1]);
                    mma16816(acc[mt][nt], Alo[mt], bh[0], bh[1]);
                }
        }

        if (s + 1 < S) stage_store(sbase, (s + 1) & 1, lrow, lc, pa, pb);
        __syncthreads();
    }

    // epilogue
    const int gid = lane >> 2, tig = lane & 3;
#pragma unroll
    for (int mt = 0; mt < 2; mt++)
#pragma unroll
        for (int hh = 0; hh < 2; hh++) {
            const int m = bm + wm * 32 + mt * 16 + gid + hh * 8;
            float* Crow = C + (size_t)m * ldc + bn + wn * 64 + tig * 2;
            const float* Ar = addsrc
                ? addsrc + (size_t)m * ldc + bn + wn * 64 + tig * 2 : nullptr;
#pragma unroll
            for (int nt = 0; nt < 8; nt++) {
                float vx = acc[mt][nt][hh * 2];
                float vy = acc[mt][nt][hh * 2 + 1];
                if (Ar) {
                    float2 a = *reinterpret_cast<const float2*>(Ar + nt * 8);
                    vx += a.x; vy += a.y;
                }
                if (op == 1) {
                    float2 cv = *reinterpret_cast<const float2*>(Crow + nt * 8);
                    vx += cv.x; vy += cv.y;
                }
                *reinterpret_cast<float2*>(Crow + nt * 8) = make_float2(vx, vy);
            }
        }
}

// ---------------------------------------------------------------------------
// fp32 GEMM (NT) — kept for the small dt projection (K=48)
// op: 2 = softplus(acc + bias)
// ---------------------------------------------------------------------------
__global__ __launch_bounds__(256, 2)
void sgemm_nt(int M, int N, int K,
              const float* __restrict__ A, int lda,
              const float* __restrict__ B, int ldb,
              float* __restrict__ C, int ldc,
              const float* __restrict__ addsrc,
              const float* __restrict__ bias,
              int op)
{
    __shared__ float As[8][128];
    __shared__ float Bs[8][128];
    const int tid = threadIdx.x;
    const int bm = blockIdx.y * 128;
    const int bn = blockIdx.x * 128;
    const int ir = tid >> 1;
    const int ic = (tid & 1) * 4;
    const float* Ap = A + (size_t)(bm + ir) * lda + ic;
    const float* Bp = B + (size_t)(bn + ir) * ldb + ic;

    float acc[8][8];
#pragma unroll
    for (int i = 0; i < 8; i++)
#pragma unroll
        for (int j = 0; j < 8; j++) acc[i][j] = 0.f;

    const int tr = (tid >> 4) * 8;
    const int tc = (tid & 15) * 8;

    for (int k0 = 0; k0 < K; k0 += 8) {
        float4 a4 = *reinterpret_cast<const float4*>(Ap + k0);
        float4 b4 = *reinterpret_cast<const float4*>(Bp + k0);
        As[ic + 0][ir] = a4.x; As[ic + 1][ir] = a4.y;
        As[ic + 2][ir] = a4.z; As[ic + 3][ir] = a4.w;
        Bs[ic + 0][ir] = b4.x; Bs[ic + 1][ir] = b4.y;
        Bs[ic + 2][ir] = b4.z; Bs[ic + 3][ir] = b4.w;
        __syncthreads();
#pragma unroll
        for (int k = 0; k < 8; k++) {
            float ra[8], rb[8];
            *reinterpret_cast<float4*>(&ra[0]) = *reinterpret_cast<const float4*>(&As[k][tr]);
            *reinterpret_cast<float4*>(&ra[4]) = *reinterpret_cast<const float4*>(&As[k][tr + 4]);
            *reinterpret_cast<float4*>(&rb[0]) = *reinterpret_cast<const float4*>(&Bs[k][tc]);
            *reinterpret_cast<float4*>(&rb[4]) = *reinterpret_cast<const float4*>(&Bs[k][tc + 4]);
#pragma unroll
            for (int i = 0; i < 8; i++)
#pragma unroll
                for (int j = 0; j < 8; j++)
                    acc[i][j] += ra[i] * rb[j];
        }
        __syncthreads();
    }

#pragma unroll
    for (int i = 0; i < 8; i++) {
        const int m = bm + tr + i;
#pragma unroll
        for (int j = 0; j < 8; j++) {
            const int n = bn + tc + j;
            const size_t idx = (size_t)m * ldc + n;
            float v = acc[i][j];
            if (addsrc) v += addsrc[idx];
            if (bias)   v += bias[n];
            if (op == 1) v += C[idx];
            if (op == 2) v = (v > 20.f) ? v : log1pf(expf(v));
            C[idx] = v;
        }
    }
}

// ---------------------------------------------------------------------------
// Depthwise causal conv (fwd) + anti-causal conv (bwd) + SiLU
// ---------------------------------------------------------------------------
__global__ void conv_silu_kernel(const float* __restrict__ fw, const float* __restrict__ fb,
                                 const float* __restrict__ bw, const float* __restrict__ bb)
{
    const int idx = blockIdx.x * 256 + threadIdx.x;
    const int b = idx / DI, d = idx % DI;
    const float* xzf = g_scratch + OFF_XZ_F;
    const float* xzb = g_scratch + OFF_XZ_B;
    float* xcf = g_scratch + OFF_XC_F;
    float* xcb = g_scratch + OFF_XC_B;

    float wf[4], wbk[4];
#pragma unroll
    for (int k = 0; k < 4; k++) { wf[k] = fw[k * DI + d]; wbk[k] = bw[k * DI + d]; }

    float xf[6], xb[6];
#pragma unroll
    for (int l = 0; l < 6; l++) {
        xf[l] = xzf[(size_t)(b * 6 + l) * (2 * DI) + d];
        xb[l] = xzb[(size_t)(b * 6 + l) * (2 * DI) + d];
    }
    const float cbf = fb[d], cbb = bb[d];

#pragma unroll
    for (int l = 0; l < 6; l++) {
        float af = cbf, ab = cbb;
#pragma unroll
        for (int k = 0; k < 4; k++) {
            const int lf = l + k - 3;
            if (lf >= 0) af += wf[k] * xf[lf];
            const int lb = l + 3 - k;
            if (lb < 6) ab += wbk[k] * xb[lb];
        }
        const float sf = af / (1.f + expf(-af));
        const float sb = ab / (1.f + expf(-ab));
        xcf[(size_t)(b * 6 + l) * DI + d] = sf;
        xcb[(size_t)(b * 6 + l) * DI + d] = sb;
    }
}

// ---------------------------------------------------------------------------
// x_proj GEMM, skinny-N (M=6144, N=80, K=1536), deterministic split-K=4.
// ---------------------------------------------------------------------------
__global__ __launch_bounds__(256)
void xproj_kernel(const float* __restrict__ A, const float* __restrict__ Bw,
                  float* __restrict__ Cpart)
{
    __shared__ float As[16][64];
    __shared__ float Bs[16][80];
    const int tid = threadIdx.x;
    const int bm = blockIdx.x * 64;
    const int ks = blockIdx.y;
    const int irA = tid >> 2, icA = (tid & 3) * 4;
    const int tr = (tid >> 4) * 4, tc = (tid & 15) * 5;

    float acc[4][5];
#pragma unroll
    for (int i = 0; i < 4; i++)
#pragma unroll
        for (int j = 0; j < 5; j++) acc[i][j] = 0.f;

    const int kbeg = ks * 384;
    for (int k0 = kbeg; k0 < kbeg + 384; k0 += 16) {
        float4 a4 = *reinterpret_cast<const float4*>(A + (size_t)(bm + irA) * DI + k0 + icA);
        As[icA + 0][irA] = a4.x; As[icA + 1][irA] = a4.y;
        As[icA + 2][irA] = a4.z; As[icA + 3][irA] = a4.w;
#pragma unroll
        for (int t = 0; t < 5; t++) {
            const int li = tid + t * 256;
            const int n = li >> 4, k = li & 15;
            Bs[k][n] = Bw[(size_t)n * DI + k0 + k];
        }
        __syncthreads();
#pragma unroll
        for (int k = 0; k < 16; k++) {
            float ra[4], rb[5];
#pragma unroll
            for (int i = 0; i < 4; i++) ra[i] = As[k][tr + i];
#pragma unroll
            for (int j = 0; j < 5; j++) rb[j] = Bs[k][tc + j];
#pragma unroll
            for (int i = 0; i < 4; i++)
#pragma unroll
                for (int j = 0; j < 5; j++) acc[i][j] += ra[i] * rb[j];
        }
        __syncthreads();
    }

    float* Cp = Cpart + (size_t)ks * (size_t)MR * 80;
#pragma unroll
    for (int i = 0; i < 4; i++)
#pragma unroll
        for (int j = 0; j < 5; j++)
            Cp[(size_t)(bm + tr + i) * 80 + tc + j] = acc[i][j];
}

__global__ void reduce4_kernel()
{
    const size_t S = (size_t)MR * 80;
    const size_t i = (size_t)blockIdx.x * 256 + threadIdx.x;
    const float* pf = g_scratch + OFF_XDP_F;
    const float* pb = g_scratch + OFF_XDP_B;
    g_scratch[OFF_XD_F + i] = (pf[i] + pf[i + S]) + (pf[i + 2 * S] + pf[i + 3 * S]);
    g_scratch[OFF_XD_B + i] = (pb[i] + pb[i + S]) + (pb[i + 2 * S] + pb[i + 3 * S]);
}

// ---------------------------------------------------------------------------
// Selective scan + skip (u*D) + SiLU(z) gate
// ---------------------------------------------------------------------------
__global__ __launch_bounds__(256)
void scan_kernel(int rev,
                 const float* __restrict__ dtb,
                 const float* __restrict__ ub,
                 const float* __restrict__ xzb,
                 const float* __restrict__ xdb,
                 const float* __restrict__ Alog,
                 const float* __restrict__ Dp,
                 float* __restrict__ yb)
{
    __shared__ float sB[6][16];
    __shared__ float sC[6][16];
    const int tid = threadIdx.x;
    const int b = blockIdx.y;
    const int d = blockIdx.x * 256 + tid;

    if (tid < 96) {
        const int l = tid >> 4, n = tid & 15;
        sB[l][n] = xdb[(size_t)(b * 6 + l) * 80 + 48 + n];
    } else if (tid < 192) {
        const int t = tid - 96;
        const int l = t >> 4, n = t & 15;
        sC[l][n] = xdb[(size_t)(b * 6 + l) * 80 + 64 + n];
    }
    __syncthreads();

    float A[16];
#pragma unroll
    for (int n = 0; n < 16; n++) A[n] = -expf(Alog[(size_t)d * 16 + n]);

    float h[16];
#pragma unroll
    for (int n = 0; n < 16; n++) h[n] = 0.f;
    const float Dd = Dp[d];

    for (int s = 0; s < 6; s++) {
        const int l = rev ? (5 - s) : s;
        const size_t row = (size_t)(b * 6 + l);
        const float dt = dtb[row * DI + d];
        const float u  = ub[row * DI + d];
        const float dtu = dt * u;
        float y = 0.f;
#pragma unroll
        for (int n = 0; n < 16; n++) {
            h[n] = expf(dt * A[n]) * h[n] + dtu * sB[l][n];
            y += h[n] * sC[l][n];
        }
        y += u * Dd;
        const float z = xzb[row * (2 * DI) + DI + d];
        y *= z / (1.f + expf(-z));
        yb[row * DI + d] = y;
    }
}

// ---------------------------------------------------------------------------
// LayerNorm over the residual buffer r (MR x 768) -> d_out.
// ---------------------------------------------------------------------------
__device__ __forceinline__ float block_reduce_sum(float v)
{
    __shared__ float red[8];
    const int lane = threadIdx.x & 31, w = threadIdx.x >> 5;
#pragma unroll
    for (int o = 16; o; o >>= 1) v += __shfl_xor_sync(0xffffffffu, v, o);
    __syncthreads();
    if (lane == 0) red[w] = v;
    __syncthreads();
    return (red[0] + red[1]) + (red[2] + red[3]) +
           (red[4] + red[5]) + (red[6] + red[7]);
}

__global__ __launch_bounds__(256)
void ln_kernel(const float* __restrict__ g, const float* __restrict__ bta,
               float* __restrict__ out)
{
    const int row = blockIdx.x, tid = threadIdx.x;
    const float* r = g_scratch + OFF_R + (size_t)row * DM;
    const float v0 = r[tid], v1 = r[tid + 256], v2 = r[tid + 512];
    const float tot = block_reduce_sum(v0 + v1 + v2);
    const float mu = tot * (1.f / 768.f);
    const float d0 = v0 - mu, d1 = v1 - mu, d2 = v2 - mu;
    const float tot2 = block_reduce_sum(d0 * d0 + d1 * d1 + d2 * d2);
    const float inv = rsqrtf(tot2 * (1.f / 768.f) + 1e-5f);
    float* o = out + (size_t)row * DM;
    o[tid]       = d0 * inv * g[tid]       + bta[tid];
    o[tid + 256] = d1 * inv * g[tid + 256] + bta[tid + 256];
    o[tid + 512] = d2 * inv * g[tid + 512] + bta[tid + 512];
}

// ---------------------------------------------------------------------------
// Launch
// ---------------------------------------------------------------------------
extern "C" void kernel_launch(void* const* d_in, const int* in_sizes, int n_in,
                              void* d_out, int out_size)
{
    const float* x     = (const float*)d_in[0];
    const float* f_inw = (const float*)d_in[1];
    const float* f_cw  = (const float*)d_in[2];
    const float* f_cb  = (const float*)d_in[3];
    const float* f_xp  = (const float*)d_in[4];
    const float* f_dtw = (const float*)d_in[5];
    const float* f_dtb = (const float*)d_in[6];
    const float* f_Al  = (const float*)d_in[7];
    const float* f_D   = (const float*)d_in[8];
    const float* f_ow  = (const float*)d_in[9];
    const float* b_inw = (const float*)d_in[10];
    const float* b_cw  = (const float*)d_in[11];
    const float* b_cb  = (const float*)d_in[12];
    const float* b_xp  = (const float*)d_in[13];
    const float* b_dtw = (const float*)d_in[14];
    const float* b_dtb = (const float*)d_in[15];
    const float* b_Al  = (const float*)d_in[16];
    const float* b_D   = (const float*)d_in[17];
    const float* b_ow  = (const float*)d_in[18];
    const float* ln_g  = (const float*)d_in[19];
    const float* ln_b  = (const float*)d_in[20];
    float* out = (float*)d_out;

    float* S = nullptr;
    cudaGetSymbolAddress((void**)&S, g_scratch);

    float* xz_f = S + OFF_XZ_F;
    float* xz_b = S + OFF_XZ_B;
    float* xc_f = S + OFF_XC_F;
    float* xc_b = S + OFF_XC_B;
    float* xdp_f = S + OFF_XDP_F;
    float* xdp_b = S + OFF_XDP_B;
    float* xd_f = S + OFF_XD_F;
    float* xd_b = S + OFF_XD_B;
    float* dt_f = S + OFF_DT_F;
    float* dt_b = S + OFF_DT_B;
    float* y_f  = S + OFF_Y_F;
    float* y_b  = S + OFF_Y_B;
    float* rbuf = S + OFF_R;

    cudaFuncSetAttribute(mma_gemm, cudaFuncAttributeMaxDynamicSharedMemorySize,
                         (int)MG_SMEM);

    const dim3 blk(256);

    // 1) in_proj (tensor-core split-bf16; both directions on un-reversed x)
    mma_gemm<<<dim3(24, 48), blk, MG_SMEM>>>(DM, x, DM, f_inw, DM, xz_f, 2 * DI, nullptr, 0);
    mma_gemm<<<dim3(24, 48), blk, MG_SMEM>>>(DM, x, DM, b_inw, DM, xz_b, 2 * DI, nullptr, 0);

    // 2) depthwise conv + SiLU
    conv_silu_kernel<<<BT * DI / 256, blk>>>(f_cw, f_cb, b_cw, b_cb);

    // 3) x_proj (split-K partials, deterministic reduce)
    xproj_kernel<<<dim3(96, 4), blk>>>(xc_f, f_xp, xdp_f);
    xproj_kernel<<<dim3(96, 4), blk>>>(xc_b, b_xp, xdp_b);
    reduce4_kernel<<<(int)((size_t)MR * 80 / 256), blk>>>();

    // 4) dt projection + bias + softplus (small K, keep fp32)
    sgemm_nt<<<dim3(12, 48), blk>>>(MR, DI, RK, xd_f, 80, f_dtw, RK, dt_f, DI, nullptr, f_dtb, 2);
    sgemm_nt<<<dim3(12, 48), blk>>>(MR, DI, RK, xd_b, 80, b_dtw, RK, dt_b, DI, nullptr, b_dtb, 2);

    // 5) selective scan + D skip + SiLU(z) gate
    scan_kernel<<<dim3(6, BT), blk>>>(0, dt_f, xc_f, xz_f, xd_f, f_Al, f_D, y_f);
    scan_kernel<<<dim3(6, BT), blk>>>(1, dt_b, xc_b, xz_b, xd_b, b_Al, b_D, y_b);

    // 6) out_proj (+x residual), second direction accumulates; then LayerNorm
    mma_gemm<<<dim3(6, 48), blk, MG_SMEM>>>(DI, y_f, DI, f_ow, DI, rbuf, DM, x, 0);
    mma_gemm<<<dim3(6, 48), blk, MG_SMEM>>>(DI, y_b, DI, b_ow, DI, rbuf, DM, nullptr, 1);
    ln_kernel<<<MR, blk>>>(ln_g, ln_b, out);
}